// round 2
// baseline (speedup 1.0000x reference)
#include <cuda_runtime.h>
#include <cuda_bf16.h>
#include <math_constants.h>

#define N_NODES 100000
#define N_EDGES 1600000
#define IN_FEATS 256
#define HID 128

// ---------------- device scratch (static, allocation-free) ----------------
__device__ float g_h[N_NODES * HID];      // h of current layer (reused)
__device__ float g_x2[N_NODES * HID];     // elu(layer1 out) = layer2 input
__device__ float g_el[N_NODES];
__device__ float g_er[N_NODES];
__device__ float g_s[N_NODES];            // softmax denominators
__device__ float g_w[N_EDGES];            // per-edge exp weights (CSR order)
__device__ int   g_rowptr[N_NODES + 1];
__device__ int   g_cnt[N_NODES + 1];      // counts, then cursor
__device__ int   g_csrc[N_EDGES];         // src node per CSR slot

// ---------------- CSR build ----------------
__global__ void hist_kernel(const int* __restrict__ dst, int* __restrict__ cnt, int e) {
    int i = blockIdx.x * blockDim.x + threadIdx.x;
    if (i < e) atomicAdd(&cnt[dst[i]], 1);
}

__global__ void scan_kernel(int* __restrict__ cnt, int* __restrict__ rowptr, int n) {
    // single block, 1024 threads; cnt becomes cursor (= rowptr copy)
    __shared__ int ts[1024];
    int tid = threadIdx.x;
    int chunk = (n + 1023) / 1024;
    int lo = tid * chunk;
    int hi = lo + chunk; if (hi > n) hi = n; if (lo > n) lo = n;
    int sum = 0;
    for (int i = lo; i < hi; i++) sum += cnt[i];
    ts[tid] = sum;
    __syncthreads();
    // Hillis-Steele inclusive scan
    for (int off = 1; off < 1024; off <<= 1) {
        int add = (tid >= off) ? ts[tid - off] : 0;
        __syncthreads();
        ts[tid] += add;
        __syncthreads();
    }
    int excl = ts[tid] - sum;
    int run = excl;
    for (int i = lo; i < hi; i++) {
        int c = cnt[i];
        rowptr[i] = run;
        cnt[i] = run;   // cursor
        run += c;
    }
    if (tid == 1023) rowptr[n] = run;
}

__global__ void fill_kernel(const int* __restrict__ src, const int* __restrict__ dst,
                            int* __restrict__ cursor, int* __restrict__ csrc, int e) {
    int i = blockIdx.x * blockDim.x + threadIdx.x;
    if (i < e) {
        int d = dst[i];
        int p = atomicAdd(&cursor[d], 1);
        csrc[p] = src[i];
    }
}

// ---------------- fused GEMM (h = X @ W^T) + el/er epilogue ----------------
// block = 256 threads, tile = 64 nodes x 128 cols, K-chunks of 32.
template <int K>
__global__ void __launch_bounds__(256)
gemm_kernel(const float* __restrict__ X, const float* __restrict__ W,
            const float* __restrict__ al, const float* __restrict__ ar,
            float* __restrict__ H, float* __restrict__ el, float* __restrict__ er,
            int nnodes)
{
    constexpr int KC = 32;
    __shared__ float Xs[KC][68];    // [k][node], 16B-aligned rows
    __shared__ float Ws[KC][132];   // [k][col]
    const int node0 = blockIdx.x * 64;
    const int tid = threadIdx.x;
    const int lane = tid & 31;      // col group: cols [4*lane, 4*lane+4)
    const int warp = tid >> 5;      // node group: nodes [node0+8*warp, +8)

    float acc[8][4];
#pragma unroll
    for (int n = 0; n < 8; n++)
#pragma unroll
        for (int c = 0; c < 4; c++) acc[n][c] = 0.f;

    for (int k0 = 0; k0 < K; k0 += KC) {
        // load W chunk transposed: Ws[kk][col] = W[col][k0+kk]
        {
            int kk = tid & 31;
            int c0 = tid >> 5;
#pragma unroll
            for (int p = 0; p < 16; p++) {
                int col = c0 + p * 8;
                Ws[kk][col] = W[col * K + k0 + kk];
            }
        }
        // load X chunk transposed: Xs[kk][n] = X[node0+n][k0+kk]
        {
            int kk = tid & 31;
            int n0 = tid >> 5;
#pragma unroll
            for (int p = 0; p < 8; p++) {
                int n = n0 + p * 8;
                int node = node0 + n;
                if (node >= nnodes) node = nnodes - 1;   // clamp (stores predicated later)
                Xs[kk][n] = X[node * K + k0 + kk];
            }
        }
        __syncthreads();
#pragma unroll
        for (int kk = 0; kk < KC; kk++) {
            float4 w4 = *(const float4*)&Ws[kk][lane * 4];
            float4 xa = *(const float4*)&Xs[kk][warp * 8];
            float4 xb = *(const float4*)&Xs[kk][warp * 8 + 4];
            float xv[8] = {xa.x, xa.y, xa.z, xa.w, xb.x, xb.y, xb.z, xb.w};
#pragma unroll
            for (int n = 0; n < 8; n++) {
                acc[n][0] = fmaf(xv[n], w4.x, acc[n][0]);
                acc[n][1] = fmaf(xv[n], w4.y, acc[n][1]);
                acc[n][2] = fmaf(xv[n], w4.z, acc[n][2]);
                acc[n][3] = fmaf(xv[n], w4.w, acc[n][3]);
            }
        }
        __syncthreads();
    }

    // epilogue: store h rows + warp-reduced el/er
    float4 al4 = *(const float4*)&al[lane * 4];
    float4 ar4 = *(const float4*)&ar[lane * 4];
#pragma unroll
    for (int n = 0; n < 8; n++) {
        int node = node0 + warp * 8 + n;
        bool valid = node < nnodes;
        if (valid) {
            float4 hv = make_float4(acc[n][0], acc[n][1], acc[n][2], acc[n][3]);
            *(float4*)&H[node * HID + lane * 4] = hv;
        }
        float sl = acc[n][0] * al4.x + acc[n][1] * al4.y + acc[n][2] * al4.z + acc[n][3] * al4.w;
        float sr = acc[n][0] * ar4.x + acc[n][1] * ar4.y + acc[n][2] * ar4.z + acc[n][3] * ar4.w;
#pragma unroll
        for (int off = 16; off; off >>= 1) {
            sl += __shfl_xor_sync(0xffffffffu, sl, off);
            sr += __shfl_xor_sync(0xffffffffu, sr, off);
        }
        if (valid && lane == 0) { el[node] = sl; er[node] = sr; }
    }
}

// ---------------- per-node softmax (one warp per dst node) ----------------
__global__ void attn_kernel(const int* __restrict__ rowptr, const int* __restrict__ csrc,
                            const float* __restrict__ el, const float* __restrict__ er,
                            float* __restrict__ w, float* __restrict__ s, int n)
{
    int gw = (blockIdx.x * blockDim.x + threadIdx.x) >> 5;
    int lane = threadIdx.x & 31;
    if (gw >= n) return;
    int lo = rowptr[gw], hi = rowptr[gw + 1];
    float erd = er[gw];
    float mx = -CUDART_INF_F;
    for (int j = lo + lane; j < hi; j += 32) {
        float e = el[csrc[j]] + erd;
        e = e > 0.f ? e : 0.2f * e;     // leaky_relu, slope 0.2
        w[j] = e;
        mx = fmaxf(mx, e);
    }
#pragma unroll
    for (int off = 16; off; off >>= 1)
        mx = fmaxf(mx, __shfl_xor_sync(0xffffffffu, mx, off));
    float sum = 0.f;
    for (int j = lo + lane; j < hi; j += 32) {
        float ex = __expf(w[j] - mx);
        w[j] = ex;
        sum += ex;
    }
#pragma unroll
    for (int off = 16; off; off >>= 1)
        sum += __shfl_xor_sync(0xffffffffu, sum, off);
    if (lane == 0) s[gw] = sum;
}

// ---------------- weighted gather-aggregate (one warp per dst node) ----------------
template <bool ELU>
__global__ void agg_kernel(const int* __restrict__ rowptr, const int* __restrict__ csrc,
                           const float* __restrict__ w, const float* __restrict__ s,
                           const float* __restrict__ h, const float* __restrict__ bias,
                           float* __restrict__ out, int n)
{
    int gw = (blockIdx.x * blockDim.x + threadIdx.x) >> 5;
    int lane = threadIdx.x & 31;
    if (gw >= n) return;
    int lo = rowptr[gw], hi = rowptr[gw + 1];
    const float4* __restrict__ h4 = (const float4*)h;
    float4 acc = make_float4(0.f, 0.f, 0.f, 0.f);
    for (int j = lo; j < hi; j++) {
        int srcn = __ldg(&csrc[j]);
        float wt = __ldg(&w[j]);
        float4 hv = __ldg(&h4[srcn * 32 + lane]);
        acc.x = fmaf(wt, hv.x, acc.x);
        acc.y = fmaf(wt, hv.y, acc.y);
        acc.z = fmaf(wt, hv.z, acc.z);
        acc.w = fmaf(wt, hv.w, acc.w);
    }
    float sv = s[gw];
    float inv = sv > 0.f ? 1.f / sv : 0.f;
    float4 b4 = ((const float4*)bias)[lane];
    float4 r;
    r.x = fmaf(acc.x, inv, b4.x);
    r.y = fmaf(acc.y, inv, b4.y);
    r.z = fmaf(acc.z, inv, b4.z);
    r.w = fmaf(acc.w, inv, b4.w);
    if (ELU) {
        r.x = r.x > 0.f ? r.x : __expf(r.x) - 1.f;
        r.y = r.y > 0.f ? r.y : __expf(r.y) - 1.f;
        r.z = r.z > 0.f ? r.z : __expf(r.z) - 1.f;
        r.w = r.w > 0.f ? r.w : __expf(r.w) - 1.f;
    }
    ((float4*)out)[gw * 32 + lane] = r;
}

// ---------------- launch ----------------
extern "C" void kernel_launch(void* const* d_in, const int* in_sizes, int n_in,
                              void* d_out, int out_size)
{
    const float* features = (const float*)d_in[0];
    const int*   src      = (const int*)d_in[1];
    const int*   dst      = (const int*)d_in[2];
    const float* W1       = (const float*)d_in[3];
    const float* al1      = (const float*)d_in[4];
    const float* ar1      = (const float*)d_in[5];
    const float* b1       = (const float*)d_in[6];
    const float* W2       = (const float*)d_in[7];
    const float* al2      = (const float*)d_in[8];
    const float* ar2      = (const float*)d_in[9];
    const float* b2       = (const float*)d_in[10];
    float* out = (float*)d_out;

    const int n = in_sizes[0] / IN_FEATS;   // 100000
    const int e = in_sizes[1];              // 1600000

    float *h, *x2, *el, *er, *sarr, *warr;
    int *rowptr, *cnt, *csrc;
    cudaGetSymbolAddress((void**)&h,      g_h);
    cudaGetSymbolAddress((void**)&x2,     g_x2);
    cudaGetSymbolAddress((void**)&el,     g_el);
    cudaGetSymbolAddress((void**)&er,     g_er);
    cudaGetSymbolAddress((void**)&sarr,   g_s);
    cudaGetSymbolAddress((void**)&warr,   g_w);
    cudaGetSymbolAddress((void**)&rowptr, g_rowptr);
    cudaGetSymbolAddress((void**)&cnt,    g_cnt);
    cudaGetSymbolAddress((void**)&csrc,   g_csrc);

    const int TPB = 256;
    const int eblocks = (e + TPB - 1) / TPB;
    const int nwarp_blocks = (n * 32 + TPB - 1) / TPB;
    const int gemm_blocks = (n + 63) / 64;

    // CSR build (by dst)
    cudaMemsetAsync(cnt, 0, (size_t)(n + 1) * sizeof(int));
    hist_kernel<<<eblocks, TPB>>>(dst, cnt, e);
    scan_kernel<<<1, 1024>>>(cnt, rowptr, n);
    fill_kernel<<<eblocks, TPB>>>(src, dst, cnt, csrc, e);

    // ---- layer 1 ----
    gemm_kernel<IN_FEATS><<<gemm_blocks, TPB>>>(features, W1, al1, ar1, h, el, er, n);
    attn_kernel<<<nwarp_blocks, TPB>>>(rowptr, csrc, el, er, warr, sarr, n);
    agg_kernel<true><<<nwarp_blocks, TPB>>>(rowptr, csrc, warr, sarr, h, b1, x2, n);

    // ---- layer 2 ----
    gemm_kernel<HID><<<gemm_blocks, TPB>>>(x2, W2, al2, ar2, h, el, er, n);
    attn_kernel<<<nwarp_blocks, TPB>>>(rowptr, csrc, el, er, warr, sarr, n);
    agg_kernel<false><<<nwarp_blocks, TPB>>>(rowptr, csrc, warr, sarr, h, b2, out, n);
}